// round 9
// baseline (speedup 1.0000x reference)
#include <cuda_runtime.h>
#include <cuda_bf16.h>
#include <stdint.h>

#define RBOX   500000
#define KCLS   10
#define NSCAL  (RBOX * 11)
#define NV4    (NSCAL / 4)
#define TTOP   2048
#define SCORE_T 0.05f
#define NMS_T   0.5f
#define CLS_OFF 3001.0f
#define IMG_W   1920.0f
#define IMG_H   1080.0f

#define HBASE  125542u              // bits(0.05f) >> 13
#define HBINS  4506
#define CAP    6144
#define ECAP   4096

#define RMT    512                  // k_rowmax threads
#define RMC    4                    // chunks per block
#define RMROWS 512                  // rows per chunk
#define RMB    245                  // 245 * 2048 rows >= RBOX
#define NGRP   (RBOX / 32)          // 15625 row-groups (exact)

// ---------------- device scratch ----------------
__device__ unsigned int       g_hist[HBINS];
__device__ unsigned int       g_rowmax[RBOX];
__device__ unsigned int       g_grpmax[NGRP];
__device__ unsigned int       g_done;
__device__ unsigned int       g_cutbin;
__device__ unsigned int       g_cnt;
__device__ unsigned long long g_keys[CAP];
__device__ float              g_nbox[TTOP * 4];
__device__ float              g_obox[TTOP * 4];
__device__ float              g_oscore[TTOP];
__device__ unsigned int       g_ecnt;
__device__ unsigned int       g_edges[ECAP];

// ======== kernel 1: row max + histogram + group max + fused scan (last block) ========
__global__ void __launch_bounds__(RMT) k_rowmax(const float* __restrict__ scores,
                                                const float* __restrict__ center) {
    __shared__ __align__(16) float4 srow4[RMROWS * 11 / 4];   // 22528 B
    __shared__ unsigned sh[HBINS];                            // 18024 B
    __shared__ unsigned s_last;
    __shared__ unsigned wsum[16];
    __shared__ unsigned wsuf[17];
    float* srow = (float*)srow4;
    int t = threadIdx.x;
    unsigned lane = (unsigned)t & 31u, wid = (unsigned)t >> 5;
    for (int i = t; i < HBINS; i += RMT) sh[i] = 0u;

    unsigned blockrow0 = blockIdx.x * (RMROWS * RMC);
    for (int ch = 0; ch < RMC; ch++) {
        unsigned row0 = blockrow0 + (unsigned)ch * RMROWS;
        __syncthreads();                       // srow reuse + first-iter hist-zero cover
        if (row0 < RBOX) {
            unsigned base = (row0 * 11u) / 4u; // row0 multiple of 512 -> exact
            #pragma unroll
            for (int i = 0; i < 3; i++) {      // 3*512 = 1536 >= 1408
                unsigned li = (unsigned)i * RMT + (unsigned)t;
                if (li < RMROWS * 11 / 4) {
                    unsigned gq = base + li;
                    float4 v = (gq < NV4) ? __ldg(&((const float4*)scores)[gq])
                                          : make_float4(0.f, 0.f, 0.f, 0.f);
                    srow4[li] = v;
                }
            }
        }
        __syncthreads();
        unsigned r = row0 + (unsigned)t;
        unsigned bits = 0u;
        if (r < RBOX) {
            float c = __ldg(&center[r]);
            const float* rp = srow + t * 11 + 1;
            float m = rp[0];
            #pragma unroll
            for (int k = 1; k < 10; k++) m = fmaxf(m, rp[k]);
            float fg = m * c;
            if (fg > SCORE_T) {
                bits = __float_as_uint(fg);
                unsigned bin = (bits >> 13) - HBASE;
                if (bin >= HBINS) bin = HBINS - 1;
                atomicAdd(&sh[bin], 1u);
            }
            g_rowmax[r] = bits;
        }
        // group (32 consecutive rows) max
        unsigned gmax = bits;
        #pragma unroll
        for (int off = 16; off > 0; off >>= 1)
            gmax = max(gmax, __shfl_xor_sync(0xFFFFFFFFu, gmax, off));
        unsigned grp0 = row0 + (wid << 5);
        if (lane == 0u && grp0 < RBOX) g_grpmax[grp0 >> 5] = gmax;
    }
    __syncthreads();
    for (int i = t; i < HBINS; i += RMT) {
        unsigned v = sh[i];
        if (v) atomicAdd(&g_hist[i], v);
    }
    // -------- last-block-done -> suffix scan for theta_r --------
    __threadfence();
    __syncthreads();
    if (t == 0) s_last = (atomicAdd(&g_done, 1u) == RMB - 1u) ? 1u : 0u;
    __syncthreads();
    if (!s_last) return;

    const int CH = 9;                          // 512*9 = 4608 >= HBINS
    int lo = t * CH;
    unsigned loc[CH];
    unsigned p = 0u;
    #pragma unroll
    for (int k = 0; k < CH; k++) {
        int bin = lo + k;
        unsigned v = (bin < HBINS) ? __ldcg(&g_hist[bin]) : 0u;
        loc[k] = v; p += v;
    }
    unsigned s = p;                            // warp suffix scan
    #pragma unroll
    for (int off = 1; off < 32; off <<= 1) {
        unsigned v = __shfl_down_sync(0xFFFFFFFFu, s, off);
        if (lane + off < 32) s += v;
    }
    if (lane == 0u) wsum[wid] = s;
    __syncthreads();
    if (wid == 0u) {
        unsigned ws = (lane < 16u) ? wsum[lane] : 0u;
        #pragma unroll
        for (int off = 1; off < 32; off <<= 1) {
            unsigned v = __shfl_down_sync(0xFFFFFFFFu, ws, off);
            if (lane + off < 32) ws += v;
        }
        if (lane < 16u) wsuf[lane] = ws;
    }
    __syncthreads();
    unsigned sincl = s + ((wid < 15u) ? wsuf[wid + 1] : 0u);
    unsigned total = wsuf[0];
    if (total >= TTOP) {
        unsigned above = sincl - p;
        if (above < TTOP && sincl >= TTOP) {   // unique crossing thread
            unsigned run = above;
            for (int k = CH - 1; k >= 0; k--) {
                run += loc[k];
                if (run >= TTOP) { g_cutbin = (unsigned)(lo + k); break; }
            }
        }
    } else if (t == 0) {
        g_cutbin = 0u;
    }
    // reset state for next replay
    for (int bin = t; bin < HBINS; bin += RMT) g_hist[bin] = 0u;
    if (t == 0) { g_cnt = 0u; g_ecnt = 0u; g_done = 0u; }
}

// ======== kernel 2: collect candidate keys (warp per 32-row group, skip) ========
__global__ void __launch_bounds__(256) k_collect(const float* __restrict__ scores,
                                                 const float* __restrict__ center) {
    unsigned grp = (blockIdx.x * 256u + threadIdx.x) >> 5;
    unsigned lane = threadIdx.x & 31u;
    if (grp >= NGRP) return;
    unsigned cutb = HBASE + g_cutbin;                 // theta_r bin
    unsigned gmax = __ldg(&g_grpmax[grp]);
    if ((gmax >> 13) < cutb) return;                  // ~88% of groups skip here
    unsigned r = grp * 32u + lane;                    // r < RBOX (NGRP*32 == RBOX)
    unsigned bits = __ldg(&g_rowmax[r]);
    if ((bits >> 13) < cutb) return;
    float c = __ldg(&center[r]);
    const float* rp = scores + r * 11u + 1u;
    #pragma unroll
    for (int k = 0; k < 10; k++) {
        float fg = __ldg(&rp[k]) * c;
        if (fg > SCORE_T) {
            unsigned cb = __float_as_uint(fg);
            if ((cb >> 13) >= cutb) {
                unsigned j = r * 10u + (unsigned)k;
                unsigned pos = atomicAdd(&g_cnt, 1u);
                if (pos < CAP) {
                    g_keys[pos] = ((unsigned long long)cb << 32) |
                                  (unsigned long long)(0xFFFFFFFFu - j);
                }
            }
        }
    }
}

// ======== kernel 3: rank-by-count (L1-resident keys, warp per candidate) ========
__global__ void __launch_bounds__(1024) k_rank(const float* __restrict__ boxes) {
    unsigned n = g_cnt; if (n > CAP) n = CAP;
    unsigned cand = (blockIdx.x * 1024u + threadIdx.x) >> 5;
    unsigned lane = threadIdx.x & 31u;
    if (cand >= n) return;
    unsigned long long mykey = __ldg(&g_keys[cand]);
    unsigned cnt = 0u;
    for (unsigned j = lane; j < n; j += 32u)
        cnt += (__ldg(&g_keys[j]) > mykey) ? 1u : 0u;
    #pragma unroll
    for (int off = 16; off > 0; off >>= 1)
        cnt += __shfl_xor_sync(0xFFFFFFFFu, cnt, off);
    if (lane == 0u && cnt < TTOP) {
        unsigned rank = cnt;
        unsigned j = 0xFFFFFFFFu - (unsigned)(mykey & 0xFFFFFFFFull);
        float s = __uint_as_float((unsigned)(mykey >> 32));
        unsigned r = j / 10u;
        unsigned cls = j - r * 10u;
        float x1 = boxes[r * 4 + 0], y1 = boxes[r * 4 + 1];
        float x2 = boxes[r * 4 + 2], y2 = boxes[r * 4 + 3];
        float b0 = fminf(fmaxf(x1, 0.f), IMG_W);
        float b1 = fminf(fmaxf(y1, 0.f), IMG_H);
        float b2 = fminf(fmaxf(x2, 0.f), IMG_W);
        float b3 = fminf(fmaxf(y2, 0.f), IMG_H);
        float off2 = (float)cls * CLS_OFF;
        g_obox[rank * 4 + 0] = b0; g_obox[rank * 4 + 1] = b1;
        g_obox[rank * 4 + 2] = b2; g_obox[rank * 4 + 3] = b3;
        g_nbox[rank * 4 + 0] = b0 + off2; g_nbox[rank * 4 + 1] = b1 + off2;
        g_nbox[rank * 4 + 2] = b2 + off2; g_nbox[rank * 4 + 3] = b3 + off2;
        g_oscore[rank] = s;
    }
}

// ======== kernel 4: pairwise IoU -> sparse suppression edges ========
__global__ void k_edges() {
    int bi = blockIdx.y, bj = blockIdx.x;
    if (bj < bi) return;
    __shared__ float jb[64 * 4];
    int t = threadIdx.x;                    // 64 threads
    int jbase = bj * 64;
    for (int q = t; q < 256; q += 64) jb[q] = g_nbox[jbase * 4 + q];
    __syncthreads();
    int i = bi * 64 + t;
    float ax1 = g_nbox[i * 4 + 0], ay1 = g_nbox[i * 4 + 1];
    float ax2 = g_nbox[i * 4 + 2], ay2 = g_nbox[i * 4 + 3];
    float aarea = fmaxf(ax2 - ax1, 0.f) * fmaxf(ay2 - ay1, 0.f);
    for (int q = 0; q < 64; q++) {
        int j = jbase + q;
        if (j <= i) continue;
        float bx1 = jb[q * 4 + 0], by1 = jb[q * 4 + 1];
        float bx2 = jb[q * 4 + 2], by2 = jb[q * 4 + 3];
        float barea = fmaxf(bx2 - bx1, 0.f) * fmaxf(by2 - by1, 0.f);
        float w = fmaxf(fminf(ax2, bx2) - fmaxf(ax1, bx1), 0.f);
        float h = fmaxf(fminf(ay2, by2) - fmaxf(ay1, by1), 0.f);
        float inter = w * h;
        float iou = inter / (aarea + barea - inter + 1e-9f);
        if (iou > NMS_T) {
            unsigned pos = atomicAdd(&g_ecnt, 1u);
            if (pos < ECAP) g_edges[pos] = ((unsigned)i << 16) | (unsigned)j;
        }
    }
}

// ======== kernel 5: Jacobi fixpoint NMS + output ========
__global__ void k_final(float* __restrict__ out) {
    __shared__ unsigned se[ECAP];                       // 16 KB
    __shared__ unsigned char valid[TTOP];
    __shared__ unsigned char ka[TTOP];
    __shared__ unsigned char kb[TTOP];
    __shared__ int s_changed;
    int t = threadIdx.x;
    unsigned n = g_cnt; if (n > CAP) n = CAP;
    unsigned E = g_ecnt; if (E > ECAP) E = ECAP;
    for (unsigned i = t; i < E; i += 1024) se[i] = g_edges[i];
    for (unsigned i = t; i < TTOP; i += 1024) {
        unsigned char v = (i < n && g_oscore[i] > SCORE_T) ? 1 : 0;
        valid[i] = v; ka[i] = v;
    }
    __syncthreads();
    for (int round = 0; round < TTOP; round++) {
        if (t == 0) s_changed = 0;
        for (unsigned i = t; i < TTOP; i += 1024) kb[i] = valid[i];
        __syncthreads();
        for (unsigned e = t; e < E; e += 1024) {
            unsigned v = se[e];
            unsigned i = v >> 16, j = v & 0xFFFFu;
            if (ka[i]) kb[j] = 0;
        }
        __syncthreads();
        int ch = 0;
        for (unsigned i = t; i < TTOP; i += 1024) {
            if (kb[i] != ka[i]) ch = 1;
            ka[i] = kb[i];
        }
        if (ch) s_changed = 1;
        __syncthreads();
        if (!s_changed) break;
    }
    for (unsigned i = t; i < TTOP; i += 1024) {
        bool kp = ka[i] != 0;
        out[i * 5 + 0] = kp ? g_obox[i * 4 + 0] : 0.f;
        out[i * 5 + 1] = kp ? g_obox[i * 4 + 1] : 0.f;
        out[i * 5 + 2] = kp ? g_obox[i * 4 + 2] : 0.f;
        out[i * 5 + 3] = kp ? g_obox[i * 4 + 3] : 0.f;
        out[i * 5 + 4] = kp ? g_oscore[i] : 0.f;
    }
}

// ---------------- launch ----------------
extern "C" void kernel_launch(void* const* d_in, const int* in_sizes, int n_in,
                              void* d_out, int out_size) {
    const float* boxes  = nullptr;
    const float* scores = nullptr;
    const float* center = nullptr;
    for (int i = 0; i < n_in; i++) {
        if (in_sizes[i] == RBOX * 4)       boxes  = (const float*)d_in[i];
        else if (in_sizes[i] == RBOX * 11) scores = (const float*)d_in[i];
        else if (in_sizes[i] == RBOX)      center = (const float*)d_in[i];
    }
    if (!boxes)  boxes  = (const float*)d_in[0];
    if (!scores) scores = (const float*)d_in[1];
    if (!center) center = (const float*)d_in[2];
    float* out = (float*)d_out;

    k_rowmax<<<RMB, RMT>>>(scores, center);                    // + fused theta_r scan
    k_collect<<<(NGRP * 32 + 255) / 256, 256>>>(scores, center);
    k_rank<<<(CAP * 32 + 1023) / 1024, 1024>>>(boxes);
    k_edges<<<dim3(32, 32), 64>>>();
    k_final<<<1, 1024>>>(out);
}

// round 10
// speedup vs baseline: 1.3189x; 1.3189x over previous
#include <cuda_runtime.h>
#include <cuda_bf16.h>
#include <stdint.h>

#define RBOX   500000
#define KCLS   10
#define NSCAL  (RBOX * 11)
#define NV4    (NSCAL / 4)
#define TTOP   2048
#define SCORE_T 0.05f
#define NMS_T   0.5f
#define CLS_OFF 3001.0f
#define IMG_W   1920.0f
#define IMG_H   1080.0f

#define HBASE  125542u              // bits(0.05f) >> 13
#define HBINS  4506
#define CAP    6144
#define ECAP   4096

#define RMT    512                  // k_rowmax threads
#define RMC    4                    // chunks per block
#define RMROWS 512                  // rows per chunk
#define RMB    245                  // 245 * 2048 rows >= RBOX
#define NGRP   (RBOX / 32)          // 15625 row-groups (exact)
#define EGRID  1024                 // 32x32 edge tiles

// ---------------- device scratch ----------------
__device__ unsigned int       g_hist[HBINS];
__device__ unsigned int       g_rowmax[RBOX];
__device__ unsigned int       g_grpmax[NGRP];
__device__ unsigned int       g_done;
__device__ unsigned int       g_edone;
__device__ unsigned int       g_cutbin;
__device__ unsigned int       g_cnt;
__device__ unsigned long long g_keys[CAP];
__device__ float              g_nbox[TTOP * 4];
__device__ float              g_obox[TTOP * 4];
__device__ float              g_oscore[TTOP];
__device__ unsigned int       g_ecnt;
__device__ unsigned int       g_edges[ECAP];

// ======== kernel 1: row max + histogram + group max + fused scan (last block) ========
__global__ void __launch_bounds__(RMT) k_rowmax(const float* __restrict__ scores,
                                                const float* __restrict__ center) {
    __shared__ __align__(16) float4 srow4[RMROWS * 11 / 4];   // 22528 B
    __shared__ unsigned sh[HBINS];                            // 18024 B
    __shared__ unsigned s_last;
    __shared__ unsigned wsum[16];
    __shared__ unsigned wsuf[17];
    float* srow = (float*)srow4;
    int t = threadIdx.x;
    unsigned lane = (unsigned)t & 31u, wid = (unsigned)t >> 5;
    for (int i = t; i < HBINS; i += RMT) sh[i] = 0u;

    unsigned blockrow0 = blockIdx.x * (RMROWS * RMC);
    for (int ch = 0; ch < RMC; ch++) {
        unsigned row0 = blockrow0 + (unsigned)ch * RMROWS;
        __syncthreads();                       // srow reuse + first-iter hist-zero cover
        if (row0 < RBOX) {
            unsigned base = (row0 * 11u) / 4u; // row0 multiple of 512 -> exact
            #pragma unroll
            for (int i = 0; i < 3; i++) {      // 3*512 = 1536 >= 1408
                unsigned li = (unsigned)i * RMT + (unsigned)t;
                if (li < RMROWS * 11 / 4) {
                    unsigned gq = base + li;
                    float4 v = (gq < NV4) ? __ldg(&((const float4*)scores)[gq])
                                          : make_float4(0.f, 0.f, 0.f, 0.f);
                    srow4[li] = v;
                }
            }
        }
        __syncthreads();
        unsigned r = row0 + (unsigned)t;
        unsigned bits = 0u;
        if (r < RBOX) {
            float c = __ldg(&center[r]);
            const float* rp = srow + t * 11 + 1;
            float m = rp[0];
            #pragma unroll
            for (int k = 1; k < 10; k++) m = fmaxf(m, rp[k]);
            float fg = m * c;
            if (fg > SCORE_T) {
                bits = __float_as_uint(fg);
                unsigned bin = (bits >> 13) - HBASE;
                if (bin >= HBINS) bin = HBINS - 1;
                atomicAdd(&sh[bin], 1u);
            }
            g_rowmax[r] = bits;
        }
        unsigned gmax = bits;                  // 32-row group max
        #pragma unroll
        for (int off = 16; off > 0; off >>= 1)
            gmax = max(gmax, __shfl_xor_sync(0xFFFFFFFFu, gmax, off));
        unsigned grp0 = row0 + (wid << 5);
        if (lane == 0u && grp0 < RBOX) g_grpmax[grp0 >> 5] = gmax;
    }
    __syncthreads();
    for (int i = t; i < HBINS; i += RMT) {
        unsigned v = sh[i];
        if (v) atomicAdd(&g_hist[i], v);
    }
    // -------- last-block-done -> suffix scan for theta_r --------
    __threadfence();
    __syncthreads();
    if (t == 0) s_last = (atomicAdd(&g_done, 1u) == RMB - 1u) ? 1u : 0u;
    __syncthreads();
    if (!s_last) return;

    const int CH = 9;                          // 512*9 = 4608 >= HBINS
    int lo = t * CH;
    unsigned loc[CH];
    unsigned p = 0u;
    #pragma unroll
    for (int k = 0; k < CH; k++) {
        int bin = lo + k;
        unsigned v = (bin < HBINS) ? __ldcg(&g_hist[bin]) : 0u;
        loc[k] = v; p += v;
    }
    unsigned s = p;                            // warp suffix scan
    #pragma unroll
    for (int off = 1; off < 32; off <<= 1) {
        unsigned v = __shfl_down_sync(0xFFFFFFFFu, s, off);
        if (lane + off < 32) s += v;
    }
    if (lane == 0u) wsum[wid] = s;
    __syncthreads();
    if (wid == 0u) {
        unsigned ws = (lane < 16u) ? wsum[lane] : 0u;
        #pragma unroll
        for (int off = 1; off < 32; off <<= 1) {
            unsigned v = __shfl_down_sync(0xFFFFFFFFu, ws, off);
            if (lane + off < 32) ws += v;
        }
        if (lane < 16u) wsuf[lane] = ws;
    }
    __syncthreads();
    unsigned sincl = s + ((wid < 15u) ? wsuf[wid + 1] : 0u);
    unsigned total = wsuf[0];
    if (total >= TTOP) {
        unsigned above = sincl - p;
        if (above < TTOP && sincl >= TTOP) {   // unique crossing thread
            unsigned run = above;
            for (int k = CH - 1; k >= 0; k--) {
                run += loc[k];
                if (run >= TTOP) { g_cutbin = (unsigned)(lo + k); break; }
            }
        }
    } else if (t == 0) {
        g_cutbin = 0u;
    }
    for (int bin = t; bin < HBINS; bin += RMT) g_hist[bin] = 0u;
    if (t == 0) { g_cnt = 0u; g_ecnt = 0u; g_done = 0u; }
}

// ======== kernel 2: collect candidate keys (warp per 32-row group, skip) ========
__global__ void __launch_bounds__(256) k_collect(const float* __restrict__ scores,
                                                 const float* __restrict__ center) {
    unsigned grp = (blockIdx.x * 256u + threadIdx.x) >> 5;
    unsigned lane = threadIdx.x & 31u;
    if (grp >= NGRP) return;
    unsigned cutb = HBASE + g_cutbin;                 // theta_r bin
    unsigned gmax = __ldg(&g_grpmax[grp]);
    if ((gmax >> 13) < cutb) return;                  // most groups skip here
    unsigned r = grp * 32u + lane;                    // r < RBOX (NGRP*32 == RBOX)
    unsigned bits = __ldg(&g_rowmax[r]);
    if ((bits >> 13) < cutb) return;
    float c = __ldg(&center[r]);
    const float* rp = scores + r * 11u + 1u;
    #pragma unroll
    for (int k = 0; k < 10; k++) {
        float fg = __ldg(&rp[k]) * c;
        if (fg > SCORE_T) {
            unsigned cb = __float_as_uint(fg);
            if ((cb >> 13) >= cutb) {
                unsigned j = r * 10u + (unsigned)k;
                unsigned pos = atomicAdd(&g_cnt, 1u);
                if (pos < CAP) {
                    g_keys[pos] = ((unsigned long long)cb << 32) |
                                  (unsigned long long)(0xFFFFFFFFu - j);
                }
            }
        }
    }
}

// ======== kernel 3: rank-by-count (L1-resident keys, warp per candidate) ========
__global__ void __launch_bounds__(1024) k_rank(const float* __restrict__ boxes) {
    unsigned n = g_cnt; if (n > CAP) n = CAP;
    unsigned cand = (blockIdx.x * 1024u + threadIdx.x) >> 5;
    unsigned lane = threadIdx.x & 31u;
    if (cand >= n) return;
    unsigned long long mykey = __ldg(&g_keys[cand]);
    unsigned cnt = 0u;
    for (unsigned j = lane; j < n; j += 32u)
        cnt += (__ldg(&g_keys[j]) > mykey) ? 1u : 0u;
    #pragma unroll
    for (int off = 16; off > 0; off >>= 1)
        cnt += __shfl_xor_sync(0xFFFFFFFFu, cnt, off);
    if (lane == 0u && cnt < TTOP) {
        unsigned rank = cnt;
        unsigned j = 0xFFFFFFFFu - (unsigned)(mykey & 0xFFFFFFFFull);
        float s = __uint_as_float((unsigned)(mykey >> 32));
        unsigned r = j / 10u;
        unsigned cls = j - r * 10u;
        float x1 = boxes[r * 4 + 0], y1 = boxes[r * 4 + 1];
        float x2 = boxes[r * 4 + 2], y2 = boxes[r * 4 + 3];
        float b0 = fminf(fmaxf(x1, 0.f), IMG_W);
        float b1 = fminf(fmaxf(y1, 0.f), IMG_H);
        float b2 = fminf(fmaxf(x2, 0.f), IMG_W);
        float b3 = fminf(fmaxf(y2, 0.f), IMG_H);
        float off2 = (float)cls * CLS_OFF;
        g_obox[rank * 4 + 0] = b0; g_obox[rank * 4 + 1] = b1;
        g_obox[rank * 4 + 2] = b2; g_obox[rank * 4 + 3] = b3;
        g_nbox[rank * 4 + 0] = b0 + off2; g_nbox[rank * 4 + 1] = b1 + off2;
        g_nbox[rank * 4 + 2] = b2 + off2; g_nbox[rank * 4 + 3] = b3 + off2;
        g_oscore[rank] = s;
    }
}

// ======== kernel 4: IoU edges (division-free filter) + fused Jacobi NMS + output ========
__global__ void __launch_bounds__(256) k_edges(float* __restrict__ out) {
    __shared__ float ib[64 * 4], jb[64 * 4];
    int t = threadIdx.x;
    int bi = blockIdx.y, bj = blockIdx.x;
    if (bj >= bi) {
        int ibase = bi * 64, jbase = bj * 64;
        if (t < 256) { ib[t] = g_nbox[ibase * 4 + t]; jb[t] = g_nbox[jbase * 4 + t]; }
        __syncthreads();
        int io = t >> 2;                     // 0..63
        int i = ibase + io;
        float ax1 = ib[io * 4 + 0], ay1 = ib[io * 4 + 1];
        float ax2 = ib[io * 4 + 2], ay2 = ib[io * 4 + 3];
        float aarea = fmaxf(ax2 - ax1, 0.f) * fmaxf(ay2 - ay1, 0.f);
        #pragma unroll
        for (int k = 0; k < 16; k++) {
            int jo = (t & 3) + 4 * k;        // 0..63
            int j = jbase + jo;
            if (j <= i) continue;
            float bx1 = jb[jo * 4 + 0], by1 = jb[jo * 4 + 1];
            float bx2 = jb[jo * 4 + 2], by2 = jb[jo * 4 + 3];
            float w = fminf(ax2, bx2) - fmaxf(ax1, bx1);
            float h = fminf(ay2, by2) - fmaxf(ay1, by1);
            if (w > 0.f && h > 0.f) {        // overlap pre-filter (kills ~99%)
                float inter = w * h;
                float barea = fmaxf(bx2 - bx1, 0.f) * fmaxf(by2 - by1, 0.f);
                float denom = aarea + barea - inter + 1e-9f;
                if (inter > 0.45f * denom) {            // multiply pre-filter
                    float iou = inter / denom;          // exact IEEE div (rare)
                    if (iou > NMS_T) {
                        unsigned pos = atomicAdd(&g_ecnt, 1u);
                        if (pos < ECAP) g_edges[pos] = ((unsigned)i << 16) | (unsigned)j;
                    }
                }
            }
        }
    }
    // -------- last-block-done -> Jacobi fixpoint NMS + output --------
    __shared__ unsigned s_last;
    __threadfence();
    __syncthreads();
    if (t == 0) s_last = (atomicAdd(&g_edone, 1u) == EGRID - 1u) ? 1u : 0u;
    __syncthreads();
    if (!s_last) return;
    {
        __shared__ unsigned se[ECAP];                   // 16 KB
        __shared__ unsigned char valid[TTOP];
        __shared__ unsigned char ka[TTOP];
        __shared__ unsigned char kb[TTOP];
        __shared__ int s_changed;
        unsigned n = g_cnt; if (n > CAP) n = CAP;
        unsigned E = __ldcg(&g_ecnt); if (E > ECAP) E = ECAP;
        for (unsigned i = t; i < E; i += 256) se[i] = __ldcg(&g_edges[i]);
        for (unsigned i = t; i < TTOP; i += 256) {
            unsigned char v = (i < n && g_oscore[i] > SCORE_T) ? 1 : 0;
            valid[i] = v; ka[i] = v;
        }
        __syncthreads();
        for (int round = 0; round < TTOP; round++) {
            if (t == 0) s_changed = 0;
            for (unsigned i = t; i < TTOP; i += 256) kb[i] = valid[i];
            __syncthreads();
            for (unsigned e = t; e < E; e += 256) {
                unsigned v = se[e];
                unsigned i = v >> 16, j = v & 0xFFFFu;
                if (ka[i]) kb[j] = 0;
            }
            __syncthreads();
            int ch = 0;
            for (unsigned i = t; i < TTOP; i += 256) {
                if (kb[i] != ka[i]) ch = 1;
                ka[i] = kb[i];
            }
            if (ch) s_changed = 1;
            __syncthreads();
            if (!s_changed) break;
        }
        for (unsigned i = t; i < TTOP; i += 256) {
            bool kp = ka[i] != 0;
            out[i * 5 + 0] = kp ? g_obox[i * 4 + 0] : 0.f;
            out[i * 5 + 1] = kp ? g_obox[i * 4 + 1] : 0.f;
            out[i * 5 + 2] = kp ? g_obox[i * 4 + 2] : 0.f;
            out[i * 5 + 3] = kp ? g_obox[i * 4 + 3] : 0.f;
            out[i * 5 + 4] = kp ? g_oscore[i] : 0.f;
        }
        if (t == 0) g_edone = 0u;              // reset for next replay
    }
}

// ---------------- launch ----------------
extern "C" void kernel_launch(void* const* d_in, const int* in_sizes, int n_in,
                              void* d_out, int out_size) {
    const float* boxes  = nullptr;
    const float* scores = nullptr;
    const float* center = nullptr;
    for (int i = 0; i < n_in; i++) {
        if (in_sizes[i] == RBOX * 4)       boxes  = (const float*)d_in[i];
        else if (in_sizes[i] == RBOX * 11) scores = (const float*)d_in[i];
        else if (in_sizes[i] == RBOX)      center = (const float*)d_in[i];
    }
    if (!boxes)  boxes  = (const float*)d_in[0];
    if (!scores) scores = (const float*)d_in[1];
    if (!center) center = (const float*)d_in[2];
    float* out = (float*)d_out;

    k_rowmax<<<RMB, RMT>>>(scores, center);                    // + fused theta_r scan
    k_collect<<<(NGRP * 32 + 255) / 256, 256>>>(scores, center);
    k_rank<<<(CAP * 32 + 1023) / 1024, 1024>>>(boxes);
    k_edges<<<dim3(32, 32), 256>>>(out);                       // + fused NMS/output
}